// round 1
// baseline (speedup 1.0000x reference)
#include <cuda_runtime.h>
#include <cuda_bf16.h>

// Problem constants
#define T_STEPS 256
#define BATCH   1000
#define D_IN    300
#define HID     2
#define H4      8   // 4*HID
#define ROWS    (T_STEPS * BATCH)   // 256000

// Scratch: xg[t][b][g]  (t*BATCH + b)*8 + g   -> 8.192 MB (fits L2)
__device__ float g_xg[ROWS * H4];

// ---------------------------------------------------------------------------
// Kernel A: xg = x @ W_ih0^T + (b_ih0 + b_hh0)
// One thread per (t,b) row; weights staged transposed in shared (broadcast).
// ---------------------------------------------------------------------------
__global__ __launch_bounds__(256) void xg_gemm_kernel(
    const float* __restrict__ x,      // [T,B,D_IN]
    const float* __restrict__ Wih0,   // [8, 300]
    const float* __restrict__ bih0,   // [8]
    const float* __restrict__ bhh0)   // [8]
{
    __shared__ float Wt[D_IN * H4];   // Wt[d*8+g] = W[g*300+d]
    __shared__ float Bs[H4];

    int tid = threadIdx.x;
    for (int i = tid; i < D_IN * H4; i += blockDim.x) {
        int g = i / D_IN;
        int d = i % D_IN;
        Wt[d * H4 + g] = Wih0[i];
    }
    if (tid < H4) Bs[tid] = bih0[tid] + bhh0[tid];
    __syncthreads();

    int row = blockIdx.x * blockDim.x + tid;   // 1000 blocks * 256 = 256000 exact
    const float4* xrow = reinterpret_cast<const float4*>(x + (size_t)row * D_IN);

    float acc[H4];
    #pragma unroll
    for (int g = 0; g < H4; g++) acc[g] = Bs[g];

    #pragma unroll 5
    for (int d4 = 0; d4 < D_IN / 4; d4++) {
        float4 v = xrow[d4];
        const float* ws = &Wt[d4 * 4 * H4];
        #pragma unroll
        for (int g = 0; g < H4; g++) acc[g] = fmaf(v.x, ws[0 * H4 + g], acc[g]);
        #pragma unroll
        for (int g = 0; g < H4; g++) acc[g] = fmaf(v.y, ws[1 * H4 + g], acc[g]);
        #pragma unroll
        for (int g = 0; g < H4; g++) acc[g] = fmaf(v.z, ws[2 * H4 + g], acc[g]);
        #pragma unroll
        for (int g = 0; g < H4; g++) acc[g] = fmaf(v.w, ws[3 * H4 + g], acc[g]);
    }

    float4* out = reinterpret_cast<float4*>(&g_xg[(size_t)row * H4]);
    out[0] = make_float4(acc[0], acc[1], acc[2], acc[3]);
    out[1] = make_float4(acc[4], acc[5], acc[6], acc[7]);
}

// ---------------------------------------------------------------------------
// Activations: overflow-safe fast versions (~1e-6 accurate)
// ---------------------------------------------------------------------------
__device__ __forceinline__ float sigf(float x) {
    x = fminf(fmaxf(x, -30.0f), 30.0f);
    return __fdividef(1.0f, 1.0f + __expf(-x));
}
__device__ __forceinline__ float tanh_(float x) {
    x = fminf(fmaxf(x, -15.0f), 15.0f);
    float e = __expf(-2.0f * x);
    return __fdividef(1.0f - e, 1.0f + e);
}

// ---------------------------------------------------------------------------
// Kernel B: sequential 2-layer LSTM recurrence + final linear.
// One thread per batch element; all small weights in registers.
// ---------------------------------------------------------------------------
__global__ __launch_bounds__(128) void recur_kernel(
    const float* __restrict__ h0in,  // [2, B, 2]
    const float* __restrict__ c0in,  // [2, B, 2]
    const float* __restrict__ Whh0,  // [8, 2]
    const float* __restrict__ Wih1,  // [8, 2]
    const float* __restrict__ Whh1,  // [8, 2]
    const float* __restrict__ bih1,  // [8]
    const float* __restrict__ bhh1,  // [8]
    const float* __restrict__ Wlin,  // [1, 2]
    const float* __restrict__ blin,  // [1]
    float* __restrict__ out)         // [B]
{
    int b = blockIdx.x * blockDim.x + threadIdx.x;
    if (b >= BATCH) return;

    // Load tiny weights into registers
    float whh0[H4][2], wih1[H4][2], whh1[H4][2], b1[H4];
    #pragma unroll
    for (int g = 0; g < H4; g++) {
        whh0[g][0] = __ldg(&Whh0[g * 2 + 0]);
        whh0[g][1] = __ldg(&Whh0[g * 2 + 1]);
        wih1[g][0] = __ldg(&Wih1[g * 2 + 0]);
        wih1[g][1] = __ldg(&Wih1[g * 2 + 1]);
        whh1[g][0] = __ldg(&Whh1[g * 2 + 0]);
        whh1[g][1] = __ldg(&Whh1[g * 2 + 1]);
        b1[g]      = __ldg(&bih1[g]) + __ldg(&bhh1[g]);
    }
    float wl0 = __ldg(&Wlin[0]), wl1 = __ldg(&Wlin[1]), bl = __ldg(&blin[0]);

    // Initial states (zeros in practice, but honor inputs)
    float h0a = h0in[0 * BATCH * 2 + b * 2 + 0];
    float h0b = h0in[0 * BATCH * 2 + b * 2 + 1];
    float h1a = h0in[1 * BATCH * 2 + b * 2 + 0];
    float h1b = h0in[1 * BATCH * 2 + b * 2 + 1];
    float c0a = c0in[0 * BATCH * 2 + b * 2 + 0];
    float c0b = c0in[0 * BATCH * 2 + b * 2 + 1];
    float c1a = c0in[1 * BATCH * 2 + b * 2 + 0];
    float c1b = c0in[1 * BATCH * 2 + b * 2 + 1];

    const float4* xg = reinterpret_cast<const float4*>(&g_xg[(size_t)b * H4]);
    const int stride4 = (BATCH * H4) / 4;   // float4 stride per timestep

    #pragma unroll 2
    for (int t = 0; t < T_STEPS; t++) {
        float4 v0 = xg[(size_t)t * stride4 + 0];
        float4 v1 = xg[(size_t)t * stride4 + 1];
        float pre[H4] = {v0.x, v0.y, v0.z, v0.w, v1.x, v1.y, v1.z, v1.w};

        // ---- layer 0 ----
        #pragma unroll
        for (int g = 0; g < H4; g++)
            pre[g] = fmaf(whh0[g][0], h0a, fmaf(whh0[g][1], h0b, pre[g]));

        // gate order: i(0,1) f(2,3) g(4,5) o(6,7)
        float i0 = sigf(pre[0]),  i1 = sigf(pre[1]);
        float f0 = sigf(pre[2]),  f1 = sigf(pre[3]);
        float g0 = tanh_(pre[4]), g1 = tanh_(pre[5]);
        float o0 = sigf(pre[6]),  o1 = sigf(pre[7]);
        c0a = fmaf(f0, c0a, i0 * g0);
        c0b = fmaf(f1, c0b, i1 * g1);
        h0a = o0 * tanh_(c0a);
        h0b = o1 * tanh_(c0b);

        // ---- layer 1 ----
        float pre1[H4];
        #pragma unroll
        for (int g = 0; g < H4; g++) {
            float p = fmaf(wih1[g][0], h0a, fmaf(wih1[g][1], h0b, b1[g]));
            pre1[g] = fmaf(whh1[g][0], h1a, fmaf(whh1[g][1], h1b, p));
        }
        float i0b = sigf(pre1[0]),  i1b = sigf(pre1[1]);
        float f0b = sigf(pre1[2]),  f1b = sigf(pre1[3]);
        float g0b = tanh_(pre1[4]), g1b = tanh_(pre1[5]);
        float o0b = sigf(pre1[6]),  o1b = sigf(pre1[7]);
        c1a = fmaf(f0b, c1a, i0b * g0b);
        c1b = fmaf(f1b, c1b, i1b * g1b);
        h1a = o0b * tanh_(c1a);
        h1b = o1b * tanh_(c1b);
    }

    out[b] = fmaf(wl0, h1a, fmaf(wl1, h1b, bl));
}

// ---------------------------------------------------------------------------
extern "C" void kernel_launch(void* const* d_in, const int* in_sizes, int n_in,
                              void* d_out, int out_size)
{
    const float* x     = (const float*)d_in[0];
    const float* h0    = (const float*)d_in[1];
    const float* c0    = (const float*)d_in[2];
    const float* Wih0  = (const float*)d_in[3];
    const float* Whh0  = (const float*)d_in[4];
    const float* bih0  = (const float*)d_in[5];
    const float* bhh0  = (const float*)d_in[6];
    const float* Wih1  = (const float*)d_in[7];
    const float* Whh1  = (const float*)d_in[8];
    const float* bih1  = (const float*)d_in[9];
    const float* bhh1  = (const float*)d_in[10];
    const float* Wlin  = (const float*)d_in[11];
    const float* blin  = (const float*)d_in[12];
    float* out = (float*)d_out;

    xg_gemm_kernel<<<ROWS / 256, 256>>>(x, Wih0, bih0, bhh0);
    recur_kernel<<<8, 128>>>(h0, c0, Whh0, Wih1, Whh1, bih1, bhh1, Wlin, blin, out);
}